// round 1
// baseline (speedup 1.0000x reference)
#include <cuda_runtime.h>
#include <cstdint>

// Problem constants (fixed by the dataset)
#define B_DIM   64
#define C_DIM   4
#define RXD     64
#define E_DIM   512
#define P_DIM   4
#define OSIZE   256

#define L_TOT   (RXD * E_DIM)          // 32768
#define K_TOT   (P_DIM * L_TOT)        // 131072 (fan_in)
#define M_TOT   (B_DIM * C_DIM)        // 256 rows
#define N_TOT   OSIZE                  // 256

// GEMM tiling
#define SPLITS  64
#define KC      (K_TOT / SPLITS)       // 2048
#define BM      128
#define BN      128
#define BK      16
#define LDS_PAD 20                     // smem row stride in floats (16B aligned, conflict-free)

// Scratch (device globals: allowed; no runtime allocation)
__device__ float g_cat[M_TOT * K_TOT];                 // 134 MB, tf32-rounded features
__device__ float g_part[SPLITS * M_TOT * N_TOT];       // 16.7 MB split-K partials

// ---------------------------------------------------------------------------
// Kernel 1: build cat[row][p*L + rr*E + e]
//   v(p)[row, rr, e] = x[row, rxd_perm[rr], e_idx[e,p]] * signs[e,p]
//   p=0: identity; p>=1: within each group of k=2^p consecutive positions,
//   keep first-argmax value, zero elsewhere. Values rounded to tf32 (RN).
// ---------------------------------------------------------------------------
__global__ void prep_kernel(const float* __restrict__ x,
                            const int*   __restrict__ rxd_perm,
                            const int*   __restrict__ e_idx,
                            const float* __restrict__ signs) {
    __shared__ float xs[E_DIM];
    const int rr  = blockIdx.x;   // 0..63
    const int row = blockIdx.y;   // 0..255
    const int tid = threadIdx.x;  // 256 threads

    const int rp = rxd_perm[rr];
    const float* xr = x + ((size_t)row * RXD + rp) * E_DIM;
    ((float2*)xs)[tid] = ((const float2*)xr)[tid];   // 512 floats
    __syncthreads();

    const int p     = tid >> 6;          // 0..3
    const int ebase = (tid & 63) << 3;   // 8 consecutive e's

    float v[8];
#pragma unroll
    for (int i = 0; i < 8; i++) {
        const int e = ebase + i;
        v[i] = xs[e_idx[e * P_DIM + p]] * signs[e * P_DIM + p];
    }

    float o[8];
    if (p == 0) {
#pragma unroll
        for (int i = 0; i < 8; i++) o[i] = v[i];
    } else if (p == 1) {
#pragma unroll
        for (int g = 0; g < 4; g++) {
            const float a = v[2*g], b = v[2*g + 1];
            if (b > a) { o[2*g] = 0.f; o[2*g+1] = b; }
            else       { o[2*g] = a;   o[2*g+1] = 0.f; }
        }
    } else if (p == 2) {
#pragma unroll
        for (int g = 0; g < 2; g++) {
            int idx = 0; float mx = v[4*g];
#pragma unroll
            for (int i = 1; i < 4; i++)
                if (v[4*g + i] > mx) { mx = v[4*g + i]; idx = i; }
#pragma unroll
            for (int i = 0; i < 4; i++) o[4*g + i] = (i == idx) ? mx : 0.f;
        }
    } else {
        int idx = 0; float mx = v[0];
#pragma unroll
        for (int i = 1; i < 8; i++)
            if (v[i] > mx) { mx = v[i]; idx = i; }
#pragma unroll
        for (int i = 0; i < 8; i++) o[i] = (i == idx) ? mx : 0.f;
    }

    // Round to tf32 (RN) so the MMA sees properly-rounded operands.
#pragma unroll
    for (int i = 0; i < 8; i++) {
        unsigned u;
        asm("cvt.rna.tf32.f32 %0, %1;" : "=r"(u) : "f"(o[i]));
        o[i] = __uint_as_float(u);
    }

    float* dst = g_cat + (size_t)row * K_TOT + p * L_TOT + rr * E_DIM + ebase;
    ((float4*)dst)[0] = make_float4(o[0], o[1], o[2], o[3]);
    ((float4*)dst)[1] = make_float4(o[4], o[5], o[6], o[7]);
}

// ---------------------------------------------------------------------------
// Kernel 2: split-K TF32 GEMM via mma.sync.m16n8k8
//   partial[z][m][n] = sum_{k in split z} cat[m][k] * W[n][k]
//   Both operands K-contiguous row-major -> mma row.col maps directly.
// ---------------------------------------------------------------------------
__device__ __forceinline__ void cpasync16(float* s, const float* g) {
    unsigned sa = (unsigned)__cvta_generic_to_shared(s);
    asm volatile("cp.async.cg.shared.global [%0], [%1], 16;" :: "r"(sa), "l"(g));
}

__global__ __launch_bounds__(256, 2)
void gemm_kernel(const float* __restrict__ W) {
    __shared__ float As[2][BM * LDS_PAD];
    __shared__ float Bs[2][BN * LDS_PAD];

    const int tid = threadIdx.x;
    const int n0  = blockIdx.x * BN;
    const int m0  = blockIdx.y * BM;
    const int z   = blockIdx.z;
    const int k00 = z * KC;
    const float* A = g_cat;

    // Global->smem load mapping: each thread loads 2 float4 of A and 2 of B
    const int lrow = tid >> 2;          // 0..63
    const int lcol = (tid & 3) * 4;     // 0,4,8,12

    auto loadStage = [&](int buf, int k0) {
        const float* ag = A + (size_t)(m0 + lrow) * K_TOT + k0 + lcol;
        cpasync16(&As[buf][lrow * LDS_PAD + lcol], ag);
        cpasync16(&As[buf][(lrow + 64) * LDS_PAD + lcol], ag + (size_t)64 * K_TOT);
        const float* bg = W + (size_t)(n0 + lrow) * K_TOT + k0 + lcol;
        cpasync16(&Bs[buf][lrow * LDS_PAD + lcol], bg);
        cpasync16(&Bs[buf][(lrow + 64) * LDS_PAD + lcol], bg + (size_t)64 * K_TOT);
    };

    const int warp = tid >> 5, lane = tid & 31;
    const int wm = warp >> 2;      // 0..1  (64 rows per warp)
    const int wn = warp & 3;       // 0..3  (32 cols per warp)
    const int ar = lane >> 2;      // 0..7
    const int ac = lane & 3;       // 0..3

    float acc[4][4][4];
#pragma unroll
    for (int i = 0; i < 4; i++)
#pragma unroll
        for (int j = 0; j < 4; j++)
#pragma unroll
            for (int q = 0; q < 4; q++) acc[i][j][q] = 0.f;

    loadStage(0, k00);
    asm volatile("cp.async.commit_group;");

    const int nIter = KC / BK;   // 128
    for (int it = 0; it < nIter; ++it) {
        const int cur = it & 1;
        if (it + 1 < nIter) {
            loadStage(cur ^ 1, k00 + (it + 1) * BK);
            asm volatile("cp.async.commit_group;");
            asm volatile("cp.async.wait_group 1;");
        } else {
            asm volatile("cp.async.wait_group 0;");
        }
        __syncthreads();

        const float* as = As[cur];
        const float* bs = Bs[cur];
#pragma unroll
        for (int kk = 0; kk < BK; kk += 8) {
            unsigned af[4][4];
#pragma unroll
            for (int mt = 0; mt < 4; mt++) {
                const int r = wm * 64 + mt * 16 + ar;
                af[mt][0] = __float_as_uint(as[r       * LDS_PAD + kk + ac]);
                af[mt][1] = __float_as_uint(as[(r + 8) * LDS_PAD + kk + ac]);
                af[mt][2] = __float_as_uint(as[r       * LDS_PAD + kk + ac + 4]);
                af[mt][3] = __float_as_uint(as[(r + 8) * LDS_PAD + kk + ac + 4]);
            }
            unsigned bf[4][2];
#pragma unroll
            for (int nt = 0; nt < 4; nt++) {
                const int n = wn * 32 + nt * 8 + ar;
                const float b0 = bs[n * LDS_PAD + kk + ac];
                const float b1 = bs[n * LDS_PAD + kk + ac + 4];
                asm("cvt.rna.tf32.f32 %0, %1;" : "=r"(bf[nt][0]) : "f"(b0));
                asm("cvt.rna.tf32.f32 %0, %1;" : "=r"(bf[nt][1]) : "f"(b1));
            }
#pragma unroll
            for (int mt = 0; mt < 4; mt++)
#pragma unroll
                for (int nt = 0; nt < 4; nt++) {
                    asm volatile(
                        "mma.sync.aligned.m16n8k8.row.col.f32.tf32.tf32.f32 "
                        "{%0,%1,%2,%3}, {%4,%5,%6,%7}, {%8,%9}, {%0,%1,%2,%3};"
                        : "+f"(acc[mt][nt][0]), "+f"(acc[mt][nt][1]),
                          "+f"(acc[mt][nt][2]), "+f"(acc[mt][nt][3])
                        : "r"(af[mt][0]), "r"(af[mt][1]), "r"(af[mt][2]), "r"(af[mt][3]),
                          "r"(bf[nt][0]), "r"(bf[nt][1]));
                }
        }
        __syncthreads();
    }

    // Epilogue: write partials (C fragment layout of m16n8)
    float* part = g_part + (size_t)z * (M_TOT * N_TOT);
#pragma unroll
    for (int mt = 0; mt < 4; mt++) {
        const int m = m0 + wm * 64 + mt * 16 + ar;
#pragma unroll
        for (int nt = 0; nt < 4; nt++) {
            const int n = n0 + wn * 32 + nt * 8 + 2 * ac;
            *(float2*)&part[(size_t)m * N_TOT + n]       = make_float2(acc[mt][nt][0], acc[mt][nt][1]);
            *(float2*)&part[(size_t)(m + 8) * N_TOT + n] = make_float2(acc[mt][nt][2], acc[mt][nt][3]);
        }
    }
}

// ---------------------------------------------------------------------------
// Kernel 3: deterministic split-K reduction + bias
// ---------------------------------------------------------------------------
__global__ void reduce_kernel(const float* __restrict__ bias, float* __restrict__ out) {
    const int m = blockIdx.x;    // 0..255
    const int n = threadIdx.x;   // 0..255
    float s = bias[n];
    const float* p = g_part + (size_t)m * N_TOT + n;
#pragma unroll 8
    for (int zz = 0; zz < SPLITS; zz++)
        s += p[(size_t)zz * (M_TOT * N_TOT)];
    out[(size_t)m * N_TOT + n] = s;
}

// ---------------------------------------------------------------------------
extern "C" void kernel_launch(void* const* d_in, const int* in_sizes, int n_in,
                              void* d_out, int out_size) {
    const float* x        = (const float*)d_in[0];
    const int*   rxd_perm = (const int*)  d_in[1];
    const int*   e_idx    = (const int*)  d_in[2];
    const float* signs    = (const float*)d_in[3];
    const float* W        = (const float*)d_in[4];
    const float* b        = (const float*)d_in[5];
    float* out = (float*)d_out;

    prep_kernel<<<dim3(RXD, M_TOT), 256>>>(x, rxd_perm, e_idx, signs);
    gemm_kernel<<<dim3(N_TOT / BN, M_TOT / BM, SPLITS), 256>>>(W);
    reduce_kernel<<<M_TOT, N_TOT>>>(b, out);
}

// round 2
// speedup vs baseline: 2.1145x; 2.1145x over previous
#include <cuda_runtime.h>
#include <cstdint>

// Problem constants (fixed by the dataset)
#define B_DIM   64
#define C_DIM   4
#define RXD     64
#define E_DIM   512
#define P_DIM   4
#define OSIZE   256

#define L_TOT   (RXD * E_DIM)          // 32768
#define K_TOT   (P_DIM * L_TOT)        // 131072 (fan_in)
#define M_TOT   (B_DIM * C_DIM)        // 256 rows
#define N_TOT   OSIZE                  // 256

// GEMM tiling
#define SPLITS  64
#define KC      (K_TOT / SPLITS)       // 2048
#define BM      128
#define BN      128
#define BK      16
#define LDS_PAD 20                     // smem row stride in floats (16B aligned, conflict-free)

#define ROWS_PB 8                      // rows per prep block

// Scratch (device globals: allowed; no runtime allocation)
__device__ float g_cat[M_TOT * K_TOT];                 // 134 MB, tf32-rounded features
__device__ float g_part[SPLITS * M_TOT * N_TOT];       // 16.7 MB split-K partials

// ---------------------------------------------------------------------------
// Kernel 1 (v2): build cat[row][p*L + rr*E + e]
//   v(p)[row, rr, e] = x[row, rxd_perm[rr], e_idx[e,p]] * signs[e,p]
//   p=0: identity; p>=1: within each group of k=2^p consecutive positions,
//   keep first-argmax value, zero elsewhere. Values rounded to tf32 (RN).
//
// Each block: one rr, 8 rows. Index/sign table loaded to smem once and then
// held in registers across all 8 rows (8x amortization vs v1).
// ---------------------------------------------------------------------------
__global__ __launch_bounds__(256)
void prep_kernel(const float* __restrict__ x,
                 const int*   __restrict__ rxd_perm,
                 const int*   __restrict__ e_idx,
                 const float* __restrict__ signs) {
    __shared__ float xs[ROWS_PB][E_DIM];          // 16 KB
    __shared__ int   tidx[P_DIM * E_DIM];         // 8 KB
    __shared__ float tsgn[P_DIM * E_DIM];         // 8 KB

    const int rr  = blockIdx.x;       // 0..63
    const int rb  = blockIdx.y;       // 0..31
    const int tid = threadIdx.x;      // 256

    // Load (p,e)->(src,sign) table: 2048 entries, 8 per thread.
#pragma unroll
    for (int u = 0; u < 8; u++) {
        const int j = tid + 256 * u;              // j = p*512 + e
        const int p = j >> 9, e = j & 511;
        tidx[j] = e_idx[e * P_DIM + p];
        tsgn[j] = signs[e * P_DIM + p];
    }

    const int rp = rxd_perm[rr];                  // uniform
    // Load 8 rows of x[row, rp, :] (coalesced float4).
#pragma unroll
    for (int u = 0; u < 4; u++) {
        const int j = tid + 256 * u;              // float4 index in [0,1024)
        const int r = j >> 7;                     // 128 float4 per row
        const int c = j & 127;
        const float* src = x + ((size_t)(rb * ROWS_PB + r) * RXD + rp) * E_DIM;
        ((float4*)xs[r])[c] = ((const float4*)src)[c];
    }
    __syncthreads();

    const int p     = tid >> 6;          // 0..3
    const int ebase = (tid & 63) << 3;   // 8 consecutive e's
    const int jb    = p * E_DIM + ebase;

    int   ix[8]; float sg[8];
#pragma unroll
    for (int i = 0; i < 8; i++) { ix[i] = tidx[jb + i]; sg[i] = tsgn[jb + i]; }

    for (int r = 0; r < ROWS_PB; r++) {
        float v[8];
#pragma unroll
        for (int i = 0; i < 8; i++) v[i] = xs[r][ix[i]] * sg[i];

        float o[8];
        if (p == 0) {
#pragma unroll
            for (int i = 0; i < 8; i++) o[i] = v[i];
        } else if (p == 1) {
#pragma unroll
            for (int g = 0; g < 4; g++) {
                const float a = v[2*g], b = v[2*g + 1];
                if (b > a) { o[2*g] = 0.f; o[2*g+1] = b; }
                else       { o[2*g] = a;   o[2*g+1] = 0.f; }
            }
        } else if (p == 2) {
#pragma unroll
            for (int g = 0; g < 2; g++) {
                int idx = 0; float mx = v[4*g];
#pragma unroll
                for (int i = 1; i < 4; i++)
                    if (v[4*g + i] > mx) { mx = v[4*g + i]; idx = i; }
#pragma unroll
                for (int i = 0; i < 4; i++) o[4*g + i] = (i == idx) ? mx : 0.f;
            }
        } else {
            int idx = 0; float mx = v[0];
#pragma unroll
            for (int i = 1; i < 8; i++)
                if (v[i] > mx) { mx = v[i]; idx = i; }
#pragma unroll
            for (int i = 0; i < 8; i++) o[i] = (i == idx) ? mx : 0.f;
        }

        // Round to tf32 (RN) so the MMA sees properly-rounded operands.
#pragma unroll
        for (int i = 0; i < 8; i++) {
            unsigned u;
            asm("cvt.rna.tf32.f32 %0, %1;" : "=r"(u) : "f"(o[i]));
            o[i] = __uint_as_float(u);
        }

        float* dst = g_cat + (size_t)(rb * ROWS_PB + r) * K_TOT
                   + p * L_TOT + rr * E_DIM + ebase;
        ((float4*)dst)[0] = make_float4(o[0], o[1], o[2], o[3]);
        ((float4*)dst)[1] = make_float4(o[4], o[5], o[6], o[7]);
    }
}

// ---------------------------------------------------------------------------
// Kernel 2: split-K TF32 GEMM via mma.sync.m16n8k8
//   partial[z][m][n] = sum_{k in split z} cat[m][k] * W[n][k]
// ---------------------------------------------------------------------------
__device__ __forceinline__ void cpasync16(float* s, const float* g) {
    unsigned sa = (unsigned)__cvta_generic_to_shared(s);
    asm volatile("cp.async.cg.shared.global [%0], [%1], 16;" :: "r"(sa), "l"(g));
}

__global__ __launch_bounds__(256, 2)
void gemm_kernel(const float* __restrict__ W) {
    __shared__ float As[2][BM * LDS_PAD];
    __shared__ float Bs[2][BN * LDS_PAD];

    const int tid = threadIdx.x;
    const int n0  = blockIdx.x * BN;
    const int m0  = blockIdx.y * BM;
    const int z   = blockIdx.z;
    const int k00 = z * KC;
    const float* A = g_cat;

    const int lrow = tid >> 2;          // 0..63
    const int lcol = (tid & 3) * 4;     // 0,4,8,12

    auto loadStage = [&](int buf, int k0) {
        const float* ag = A + (size_t)(m0 + lrow) * K_TOT + k0 + lcol;
        cpasync16(&As[buf][lrow * LDS_PAD + lcol], ag);
        cpasync16(&As[buf][(lrow + 64) * LDS_PAD + lcol], ag + (size_t)64 * K_TOT);
        const float* bg = W + (size_t)(n0 + lrow) * K_TOT + k0 + lcol;
        cpasync16(&Bs[buf][lrow * LDS_PAD + lcol], bg);
        cpasync16(&Bs[buf][(lrow + 64) * LDS_PAD + lcol], bg + (size_t)64 * K_TOT);
    };

    const int warp = tid >> 5, lane = tid & 31;
    const int wm = warp >> 2;      // 0..1  (64 rows per warp)
    const int wn = warp & 3;       // 0..3  (32 cols per warp)
    const int ar = lane >> 2;      // 0..7
    const int ac = lane & 3;       // 0..3

    float acc[4][4][4];
#pragma unroll
    for (int i = 0; i < 4; i++)
#pragma unroll
        for (int j = 0; j < 4; j++)
#pragma unroll
            for (int q = 0; q < 4; q++) acc[i][j][q] = 0.f;

    loadStage(0, k00);
    asm volatile("cp.async.commit_group;");

    const int nIter = KC / BK;   // 128
    for (int it = 0; it < nIter; ++it) {
        const int cur = it & 1;
        if (it + 1 < nIter) {
            loadStage(cur ^ 1, k00 + (it + 1) * BK);
            asm volatile("cp.async.commit_group;");
            asm volatile("cp.async.wait_group 1;");
        } else {
            asm volatile("cp.async.wait_group 0;");
        }
        __syncthreads();

        const float* as = As[cur];
        const float* bs = Bs[cur];
#pragma unroll
        for (int kk = 0; kk < BK; kk += 8) {
            unsigned af[4][4];
#pragma unroll
            for (int mt = 0; mt < 4; mt++) {
                const int r = wm * 64 + mt * 16 + ar;
                af[mt][0] = __float_as_uint(as[r       * LDS_PAD + kk + ac]);
                af[mt][1] = __float_as_uint(as[(r + 8) * LDS_PAD + kk + ac]);
                af[mt][2] = __float_as_uint(as[r       * LDS_PAD + kk + ac + 4]);
                af[mt][3] = __float_as_uint(as[(r + 8) * LDS_PAD + kk + ac + 4]);
            }
            unsigned bf[4][2];
#pragma unroll
            for (int nt = 0; nt < 4; nt++) {
                const int n = wn * 32 + nt * 8 + ar;
                const float b0 = bs[n * LDS_PAD + kk + ac];
                const float b1 = bs[n * LDS_PAD + kk + ac + 4];
                asm("cvt.rna.tf32.f32 %0, %1;" : "=r"(bf[nt][0]) : "f"(b0));
                asm("cvt.rna.tf32.f32 %0, %1;" : "=r"(bf[nt][1]) : "f"(b1));
            }
#pragma unroll
            for (int mt = 0; mt < 4; mt++)
#pragma unroll
                for (int nt = 0; nt < 4; nt++) {
                    asm volatile(
                        "mma.sync.aligned.m16n8k8.row.col.f32.tf32.tf32.f32 "
                        "{%0,%1,%2,%3}, {%4,%5,%6,%7}, {%8,%9}, {%0,%1,%2,%3};"
                        : "+f"(acc[mt][nt][0]), "+f"(acc[mt][nt][1]),
                          "+f"(acc[mt][nt][2]), "+f"(acc[mt][nt][3])
                        : "r"(af[mt][0]), "r"(af[mt][1]), "r"(af[mt][2]), "r"(af[mt][3]),
                          "r"(bf[nt][0]), "r"(bf[nt][1]));
                }
        }
        __syncthreads();
    }

    // Epilogue: write partials (C fragment layout of m16n8)
    float* part = g_part + (size_t)z * (M_TOT * N_TOT);
#pragma unroll
    for (int mt = 0; mt < 4; mt++) {
        const int m = m0 + wm * 64 + mt * 16 + ar;
#pragma unroll
        for (int nt = 0; nt < 4; nt++) {
            const int n = n0 + wn * 32 + nt * 8 + 2 * ac;
            *(float2*)&part[(size_t)m * N_TOT + n]       = make_float2(acc[mt][nt][0], acc[mt][nt][1]);
            *(float2*)&part[(size_t)(m + 8) * N_TOT + n] = make_float2(acc[mt][nt][2], acc[mt][nt][3]);
        }
    }
}

// ---------------------------------------------------------------------------
// Kernel 3: deterministic split-K reduction + bias
// ---------------------------------------------------------------------------
__global__ void reduce_kernel(const float* __restrict__ bias, float* __restrict__ out) {
    const int m = blockIdx.x;    // 0..255
    const int n = threadIdx.x;   // 0..255
    float s = bias[n];
    const float* p = g_part + (size_t)m * N_TOT + n;
#pragma unroll 8
    for (int zz = 0; zz < SPLITS; zz++)
        s += p[(size_t)zz * (M_TOT * N_TOT)];
    out[(size_t)m * N_TOT + n] = s;
}

// ---------------------------------------------------------------------------
extern "C" void kernel_launch(void* const* d_in, const int* in_sizes, int n_in,
                              void* d_out, int out_size) {
    const float* x        = (const float*)d_in[0];
    const int*   rxd_perm = (const int*)  d_in[1];
    const int*   e_idx    = (const int*)  d_in[2];
    const float* signs    = (const float*)d_in[3];
    const float* W        = (const float*)d_in[4];
    const float* b        = (const float*)d_in[5];
    float* out = (float*)d_out;

    prep_kernel<<<dim3(RXD, M_TOT / ROWS_PB), 256>>>(x, rxd_perm, e_idx, signs);
    gemm_kernel<<<dim3(N_TOT / BN, M_TOT / BM, SPLITS), 256>>>(W);
    reduce_kernel<<<M_TOT, N_TOT>>>(b, out);
}

// round 8
// speedup vs baseline: 2.2112x; 1.0457x over previous
#include <cuda_runtime.h>
#include <cstdint>

// Problem constants (fixed by the dataset)
#define B_DIM   64
#define C_DIM   4
#define RXD     64
#define E_DIM   512
#define P_DIM   4
#define OSIZE   256

#define L_TOT   (RXD * E_DIM)          // 32768
#define K_TOT   (P_DIM * L_TOT)        // 131072 (fan_in)
#define M_TOT   (B_DIM * C_DIM)        // 256 rows
#define N_TOT   OSIZE                  // 256

// GEMM tiling (mma.sync tf32; tcgen05 rejected by this toolchain's ptxas target)
#define SPLITS  32
#define KC      (K_TOT / SPLITS)       // 4096 K per CTA
#define BM      128
#define BN      128
#define BK      32
#define PADK    36                     // smem row stride in floats (conflict-free, 16B-aligned)
#define STAGES  3
#define STAGE_FLOATS (2 * 128 * PADK)  // A(128xPADK) + B(128xPADK) = 9216 floats = 36KB
#define GEMM_SMEM (STAGES * STAGE_FLOATS * 4)

#define ROWS_PB 8                      // rows per prep block

// Scratch (device globals: allowed; no runtime allocation)
__device__ float g_cat[M_TOT * K_TOT];                 // 134 MB, tf32-rounded features
__device__ float g_part[SPLITS * M_TOT * N_TOT];       // 8.4 MB split-K partials

// ---------------------------------------------------------------------------
// Kernel 1: build cat  (unchanged — 35.7us)
// ---------------------------------------------------------------------------
__global__ __launch_bounds__(256)
void prep_kernel(const float* __restrict__ x,
                 const int*   __restrict__ rxd_perm,
                 const int*   __restrict__ e_idx,
                 const float* __restrict__ signs) {
    __shared__ float xs[ROWS_PB][E_DIM];
    __shared__ int   tidx[P_DIM * E_DIM];
    __shared__ float tsgn[P_DIM * E_DIM];

    const int rr  = blockIdx.x;
    const int rb  = blockIdx.y;
    const int tid = threadIdx.x;

#pragma unroll
    for (int u = 0; u < 8; u++) {
        const int j = tid + 256 * u;
        const int p = j >> 9, e = j & 511;
        tidx[j] = e_idx[e * P_DIM + p];
        tsgn[j] = signs[e * P_DIM + p];
    }

    const int rp = rxd_perm[rr];
#pragma unroll
    for (int u = 0; u < 4; u++) {
        const int j = tid + 256 * u;
        const int r = j >> 7;
        const int c = j & 127;
        const float* src = x + ((size_t)(rb * ROWS_PB + r) * RXD + rp) * E_DIM;
        ((float4*)xs[r])[c] = ((const float4*)src)[c];
    }
    __syncthreads();

    const int p     = tid >> 6;
    const int ebase = (tid & 63) << 3;
    const int jb    = p * E_DIM + ebase;

    int   ix[8]; float sg[8];
#pragma unroll
    for (int i = 0; i < 8; i++) { ix[i] = tidx[jb + i]; sg[i] = tsgn[jb + i]; }

    for (int r = 0; r < ROWS_PB; r++) {
        float v[8];
#pragma unroll
        for (int i = 0; i < 8; i++) v[i] = xs[r][ix[i]] * sg[i];

        float o[8];
        if (p == 0) {
#pragma unroll
            for (int i = 0; i < 8; i++) o[i] = v[i];
        } else if (p == 1) {
#pragma unroll
            for (int g = 0; g < 4; g++) {
                const float a = v[2*g], b = v[2*g + 1];
                if (b > a) { o[2*g] = 0.f; o[2*g+1] = b; }
                else       { o[2*g] = a;   o[2*g+1] = 0.f; }
            }
        } else if (p == 2) {
#pragma unroll
            for (int g = 0; g < 2; g++) {
                int idx = 0; float mx = v[4*g];
#pragma unroll
                for (int i = 1; i < 4; i++)
                    if (v[4*g + i] > mx) { mx = v[4*g + i]; idx = i; }
#pragma unroll
                for (int i = 0; i < 4; i++) o[4*g + i] = (i == idx) ? mx : 0.f;
            }
        } else {
            int idx = 0; float mx = v[0];
#pragma unroll
            for (int i = 1; i < 8; i++)
                if (v[i] > mx) { mx = v[i]; idx = i; }
#pragma unroll
            for (int i = 0; i < 8; i++) o[i] = (i == idx) ? mx : 0.f;
        }

#pragma unroll
        for (int i = 0; i < 8; i++) {
            unsigned u;
            asm("cvt.rna.tf32.f32 %0, %1;" : "=r"(u) : "f"(o[i]));
            o[i] = __uint_as_float(u);
        }

        float* dst = g_cat + (size_t)(rb * ROWS_PB + r) * K_TOT
                   + p * L_TOT + rr * E_DIM + ebase;
        ((float4*)dst)[0] = make_float4(o[0], o[1], o[2], o[3]);
        ((float4*)dst)[1] = make_float4(o[4], o[5], o[6], o[7]);
    }
}

// ---------------------------------------------------------------------------
// Kernel 2: split-K TF32 GEMM via mma.sync.m16n8k8
//   v3: occ-1 (255 regs, no spills), 3-stage cp.async, BK=32, 128-CTA wave
// ---------------------------------------------------------------------------
__device__ __forceinline__ void cpasync16(float* s, const float* g) {
    unsigned sa = (unsigned)__cvta_generic_to_shared(s);
    asm volatile("cp.async.cg.shared.global [%0], [%1], 16;" :: "r"(sa), "l"(g));
}

__global__ __launch_bounds__(256, 1)
void gemm_kernel(const float* __restrict__ W) {
    extern __shared__ float smem[];   // STAGES x [ A(128xPADK) | B(128xPADK) ]

    const int tid = threadIdx.x;
    const int n0  = blockIdx.x * BN;
    const int m0  = blockIdx.y * BM;
    const int z   = blockIdx.z;
    const int k00 = z * KC;
    const float* A = g_cat;

    // Global->smem mapping: 4096 floats per operand per stage = 1024 float4.
    // 256 threads x 4 float4 each; row = j>>3 (8 float4 per 32-float row).
    const int lrow = tid >> 3;          // 0..31 (base row step 32)
    const int lcol = (tid & 7) * 4;     // 0,4,...,28

    auto loadStage = [&](int slot, int s) {
        const int k0 = k00 + s * BK;
        float* As = smem + slot * STAGE_FLOATS;
        float* Bs = As + 128 * PADK;
#pragma unroll
        for (int u = 0; u < 4; u++) {
            const int r = lrow + 32 * u;
            cpasync16(&As[r * PADK + lcol], A + (size_t)(m0 + r) * K_TOT + k0 + lcol);
        }
#pragma unroll
        for (int u = 0; u < 4; u++) {
            const int n = lrow + 32 * u;
            cpasync16(&Bs[n * PADK + lcol], W + (size_t)(n0 + n) * K_TOT + k0 + lcol);
        }
        asm volatile("cp.async.commit_group;");
    };

    const int warp = tid >> 5, lane = tid & 31;
    const int wm = warp >> 2;      // 0..1  (64 rows per warp)
    const int wn = warp & 3;       // 0..3  (32 cols per warp)
    const int ar = lane >> 2;      // 0..7
    const int ac = lane & 3;       // 0..3

    float acc[4][4][4];
#pragma unroll
    for (int i = 0; i < 4; i++)
#pragma unroll
        for (int j = 0; j < 4; j++)
#pragma unroll
            for (int q = 0; q < 4; q++) acc[i][j][q] = 0.f;

    loadStage(0, 0);
    loadStage(1, 1);

    const int nIter = KC / BK;   // 128
    for (int it = 0; it < nIter; ++it) {
        __syncthreads();   // slot (it+2)%3 compute (stage it-1) fully drained
        if (it + 2 < nIter) {
            loadStage((it + 2) % STAGES, it + 2);
            asm volatile("cp.async.wait_group 2;");
        } else if (it + 1 < nIter) {
            asm volatile("cp.async.wait_group 1;");
        } else {
            asm volatile("cp.async.wait_group 0;");
        }
        __syncthreads();

        const float* as = smem + (it % STAGES) * STAGE_FLOATS;
        const float* bs = as + 128 * PADK;
#pragma unroll
        for (int kk = 0; kk < BK; kk += 8) {
            unsigned af[4][4];
#pragma unroll
            for (int mt = 0; mt < 4; mt++) {
                const int r = wm * 64 + mt * 16 + ar;
                af[mt][0] = __float_as_uint(as[r       * PADK + kk + ac]);
                af[mt][1] = __float_as_uint(as[(r + 8) * PADK + kk + ac]);
                af[mt][2] = __float_as_uint(as[r       * PADK + kk + ac + 4]);
                af[mt][3] = __float_as_uint(as[(r + 8) * PADK + kk + ac + 4]);
            }
            unsigned bf[4][2];
#pragma unroll
            for (int nt = 0; nt < 4; nt++) {
                const int n = wn * 32 + nt * 8 + ar;
                const float b0 = bs[n * PADK + kk + ac];
                const float b1 = bs[n * PADK + kk + ac + 4];
                asm("cvt.rna.tf32.f32 %0, %1;" : "=r"(bf[nt][0]) : "f"(b0));
                asm("cvt.rna.tf32.f32 %0, %1;" : "=r"(bf[nt][1]) : "f"(b1));
            }
#pragma unroll
            for (int mt = 0; mt < 4; mt++)
#pragma unroll
                for (int nt = 0; nt < 4; nt++) {
                    asm volatile(
                        "mma.sync.aligned.m16n8k8.row.col.f32.tf32.tf32.f32 "
                        "{%0,%1,%2,%3}, {%4,%5,%6,%7}, {%8,%9}, {%0,%1,%2,%3};"
                        : "+f"(acc[mt][nt][0]), "+f"(acc[mt][nt][1]),
                          "+f"(acc[mt][nt][2]), "+f"(acc[mt][nt][3])
                        : "r"(af[mt][0]), "r"(af[mt][1]), "r"(af[mt][2]), "r"(af[mt][3]),
                          "r"(bf[nt][0]), "r"(bf[nt][1]));
                }
        }
    }

    // Epilogue: write partials (C fragment layout of m16n8)
    float* part = g_part + (size_t)z * (M_TOT * N_TOT);
#pragma unroll
    for (int mt = 0; mt < 4; mt++) {
        const int m = m0 + wm * 64 + mt * 16 + ar;
#pragma unroll
        for (int nt = 0; nt < 4; nt++) {
            const int n = n0 + wn * 32 + nt * 8 + 2 * ac;
            *(float2*)&part[(size_t)m * N_TOT + n]       = make_float2(acc[mt][nt][0], acc[mt][nt][1]);
            *(float2*)&part[(size_t)(m + 8) * N_TOT + n] = make_float2(acc[mt][nt][2], acc[mt][nt][3]);
        }
    }
}

// ---------------------------------------------------------------------------
// Kernel 3: deterministic split-K reduction + bias
// ---------------------------------------------------------------------------
__global__ void reduce_kernel(const float* __restrict__ bias, float* __restrict__ out) {
    const int m = blockIdx.x;
    const int n = threadIdx.x;
    float s = bias[n];
    const float* p = g_part + (size_t)m * N_TOT + n;
#pragma unroll 8
    for (int zz = 0; zz < SPLITS; zz++)
        s += p[(size_t)zz * (M_TOT * N_TOT)];
    out[(size_t)m * N_TOT + n] = s;
}

// ---------------------------------------------------------------------------
extern "C" void kernel_launch(void* const* d_in, const int* in_sizes, int n_in,
                              void* d_out, int out_size) {
    const float* x        = (const float*)d_in[0];
    const int*   rxd_perm = (const int*)  d_in[1];
    const int*   e_idx    = (const int*)  d_in[2];
    const float* signs    = (const float*)d_in[3];
    const float* W        = (const float*)d_in[4];
    const float* b        = (const float*)d_in[5];
    float* out = (float*)d_out;

    cudaFuncSetAttribute(gemm_kernel, cudaFuncAttributeMaxDynamicSharedMemorySize, GEMM_SMEM);

    prep_kernel<<<dim3(RXD, M_TOT / ROWS_PB), 256>>>(x, rxd_perm, e_idx, signs);
    gemm_kernel<<<dim3(N_TOT / BN, M_TOT / BM, SPLITS), 256, GEMM_SMEM>>>(W);
    reduce_kernel<<<M_TOT, N_TOT>>>(b, out);
}

// round 9
// speedup vs baseline: 2.4999x; 1.1306x over previous
#include <cuda_runtime.h>
#include <cstdint>

// Problem constants (fixed by the dataset)
#define B_DIM   64
#define C_DIM   4
#define RXD     64
#define E_DIM   512
#define P_DIM   4
#define OSIZE   256

#define L_TOT   (RXD * E_DIM)          // 32768
#define K_TOT   (P_DIM * L_TOT)        // 131072 (fan_in)
#define M_TOT   (B_DIM * C_DIM)        // 256 rows
#define N_TOT   OSIZE                  // 256

// GEMM tiling (legacy mma.sync tf32 path; rate = 256 MACs/cyc/SM measured).
// 37 uneven K-splits so grid = 2x2x37 = 148 CTAs = exactly one full wave.
#define SPLITS  37
#define NCHUNK  4096                   // total BK-chunks = K_TOT / BK
#define CHUNK_Q 110                    // NCHUNK / SPLITS
#define CHUNK_R 26                     // NCHUNK % SPLITS  (first 26 splits get 111)
#define BM      128
#define BN      128
#define BK      32
#define PADK    36                     // smem row stride in floats (conflict-free, 16B-aligned)
#define STAGES  3
#define STAGE_FLOATS (2 * 128 * PADK)  // A(128xPADK) + B(128xPADK) = 9216 floats = 36KB
#define GEMM_SMEM (STAGES * STAGE_FLOATS * 4)

#define ROWS_PB 8                      // rows per prep block

// Scratch (device globals: allowed; no runtime allocation)
__device__ float g_cat[M_TOT * K_TOT];                 // 134 MB, tf32-rounded features
__device__ float g_part[SPLITS * M_TOT * N_TOT];       // 9.7 MB split-K partials

// ---------------------------------------------------------------------------
// Kernel 1: build cat  (unchanged — 36us, near its memory floor)
// ---------------------------------------------------------------------------
__global__ __launch_bounds__(256)
void prep_kernel(const float* __restrict__ x,
                 const int*   __restrict__ rxd_perm,
                 const int*   __restrict__ e_idx,
                 const float* __restrict__ signs) {
    __shared__ float xs[ROWS_PB][E_DIM];
    __shared__ int   tidx[P_DIM * E_DIM];
    __shared__ float tsgn[P_DIM * E_DIM];

    const int rr  = blockIdx.x;
    const int rb  = blockIdx.y;
    const int tid = threadIdx.x;

#pragma unroll
    for (int u = 0; u < 8; u++) {
        const int j = tid + 256 * u;
        const int p = j >> 9, e = j & 511;
        tidx[j] = e_idx[e * P_DIM + p];
        tsgn[j] = signs[e * P_DIM + p];
    }

    const int rp = rxd_perm[rr];
#pragma unroll
    for (int u = 0; u < 4; u++) {
        const int j = tid + 256 * u;
        const int r = j >> 7;
        const int c = j & 127;
        const float* src = x + ((size_t)(rb * ROWS_PB + r) * RXD + rp) * E_DIM;
        ((float4*)xs[r])[c] = ((const float4*)src)[c];
    }
    __syncthreads();

    const int p     = tid >> 6;
    const int ebase = (tid & 63) << 3;
    const int jb    = p * E_DIM + ebase;

    int   ix[8]; float sg[8];
#pragma unroll
    for (int i = 0; i < 8; i++) { ix[i] = tidx[jb + i]; sg[i] = tsgn[jb + i]; }

    for (int r = 0; r < ROWS_PB; r++) {
        float v[8];
#pragma unroll
        for (int i = 0; i < 8; i++) v[i] = xs[r][ix[i]] * sg[i];

        float o[8];
        if (p == 0) {
#pragma unroll
            for (int i = 0; i < 8; i++) o[i] = v[i];
        } else if (p == 1) {
#pragma unroll
            for (int g = 0; g < 4; g++) {
                const float a = v[2*g], b = v[2*g + 1];
                if (b > a) { o[2*g] = 0.f; o[2*g+1] = b; }
                else       { o[2*g] = a;   o[2*g+1] = 0.f; }
            }
        } else if (p == 2) {
#pragma unroll
            for (int g = 0; g < 2; g++) {
                int idx = 0; float mx = v[4*g];
#pragma unroll
                for (int i = 1; i < 4; i++)
                    if (v[4*g + i] > mx) { mx = v[4*g + i]; idx = i; }
#pragma unroll
                for (int i = 0; i < 4; i++) o[4*g + i] = (i == idx) ? mx : 0.f;
            }
        } else {
            int idx = 0; float mx = v[0];
#pragma unroll
            for (int i = 1; i < 8; i++)
                if (v[i] > mx) { mx = v[i]; idx = i; }
#pragma unroll
            for (int i = 0; i < 8; i++) o[i] = (i == idx) ? mx : 0.f;
        }

#pragma unroll
        for (int i = 0; i < 8; i++) {
            unsigned u;
            asm("cvt.rna.tf32.f32 %0, %1;" : "=r"(u) : "f"(o[i]));
            o[i] = __uint_as_float(u);
        }

        float* dst = g_cat + (size_t)(rb * ROWS_PB + r) * K_TOT
                   + p * L_TOT + rr * E_DIM + ebase;
        ((float4*)dst)[0] = make_float4(o[0], o[1], o[2], o[3]);
        ((float4*)dst)[1] = make_float4(o[4], o[5], o[6], o[7]);
    }
}

// ---------------------------------------------------------------------------
// Kernel 2: split-K TF32 GEMM via mma.sync.m16n8k8
//   v4: 148-CTA single wave via 37 uneven K-splits (111/110 BK-chunks each)
// ---------------------------------------------------------------------------
__device__ __forceinline__ void cpasync16(float* s, const float* g) {
    unsigned sa = (unsigned)__cvta_generic_to_shared(s);
    asm volatile("cp.async.cg.shared.global [%0], [%1], 16;" :: "r"(sa), "l"(g));
}

__global__ __launch_bounds__(256, 1)
void gemm_kernel(const float* __restrict__ W) {
    extern __shared__ float smem[];   // STAGES x [ A(128xPADK) | B(128xPADK) ]

    const int tid = threadIdx.x;
    const int n0  = blockIdx.x * BN;
    const int m0  = blockIdx.y * BM;
    const int z   = blockIdx.z;

    // Uneven split: first CHUNK_R splits take CHUNK_Q+1 chunks.
    const int base  = z * CHUNK_Q + (z < CHUNK_R ? z : CHUNK_R);
    const int nIter = CHUNK_Q + (z < CHUNK_R ? 1 : 0);
    const int k00   = base * BK;

    const float* A = g_cat;

    // Global->smem mapping: 4096 floats per operand per stage = 1024 float4.
    const int lrow = tid >> 3;          // 0..31 (base row, step 32)
    const int lcol = (tid & 7) * 4;     // 0,4,...,28

    auto loadStage = [&](int slot, int s) {
        const int k0 = k00 + s * BK;
        float* As = smem + slot * STAGE_FLOATS;
        float* Bs = As + 128 * PADK;
#pragma unroll
        for (int u = 0; u < 4; u++) {
            const int r = lrow + 32 * u;
            cpasync16(&As[r * PADK + lcol], A + (size_t)(m0 + r) * K_TOT + k0 + lcol);
        }
#pragma unroll
        for (int u = 0; u < 4; u++) {
            const int n = lrow + 32 * u;
            cpasync16(&Bs[n * PADK + lcol], W + (size_t)(n0 + n) * K_TOT + k0 + lcol);
        }
        asm volatile("cp.async.commit_group;");
    };

    const int warp = tid >> 5, lane = tid & 31;
    const int wm = warp >> 2;      // 0..1  (64 rows per warp)
    const int wn = warp & 3;       // 0..3  (32 cols per warp)
    const int ar = lane >> 2;      // 0..7
    const int ac = lane & 3;       // 0..3

    float acc[4][4][4];
#pragma unroll
    for (int i = 0; i < 4; i++)
#pragma unroll
        for (int j = 0; j < 4; j++)
#pragma unroll
            for (int q = 0; q < 4; q++) acc[i][j][q] = 0.f;

    loadStage(0, 0);
    loadStage(1, 1);

    for (int it = 0; it < nIter; ++it) {
        __syncthreads();   // slot (it+2)%3 compute (stage it-1) fully drained
        if (it + 2 < nIter) {
            loadStage((it + 2) % STAGES, it + 2);
            asm volatile("cp.async.wait_group 2;");
        } else if (it + 1 < nIter) {
            asm volatile("cp.async.wait_group 1;");
        } else {
            asm volatile("cp.async.wait_group 0;");
        }
        __syncthreads();

        const float* as = smem + (it % STAGES) * STAGE_FLOATS;
        const float* bs = as + 128 * PADK;
#pragma unroll
        for (int kk = 0; kk < BK; kk += 8) {
            unsigned af[4][4];
#pragma unroll
            for (int mt = 0; mt < 4; mt++) {
                const int r = wm * 64 + mt * 16 + ar;
                af[mt][0] = __float_as_uint(as[r       * PADK + kk + ac]);
                af[mt][1] = __float_as_uint(as[(r + 8) * PADK + kk + ac]);
                af[mt][2] = __float_as_uint(as[r       * PADK + kk + ac + 4]);
                af[mt][3] = __float_as_uint(as[(r + 8) * PADK + kk + ac + 4]);
            }
            unsigned bf[4][2];
#pragma unroll
            for (int nt = 0; nt < 4; nt++) {
                const int n = wn * 32 + nt * 8 + ar;
                const float b0 = bs[n * PADK + kk + ac];
                const float b1 = bs[n * PADK + kk + ac + 4];
                asm("cvt.rna.tf32.f32 %0, %1;" : "=r"(bf[nt][0]) : "f"(b0));
                asm("cvt.rna.tf32.f32 %0, %1;" : "=r"(bf[nt][1]) : "f"(b1));
            }
#pragma unroll
            for (int mt = 0; mt < 4; mt++)
#pragma unroll
                for (int nt = 0; nt < 4; nt++) {
                    asm volatile(
                        "mma.sync.aligned.m16n8k8.row.col.f32.tf32.tf32.f32 "
                        "{%0,%1,%2,%3}, {%4,%5,%6,%7}, {%8,%9}, {%0,%1,%2,%3};"
                        : "+f"(acc[mt][nt][0]), "+f"(acc[mt][nt][1]),
                          "+f"(acc[mt][nt][2]), "+f"(acc[mt][nt][3])
                        : "r"(af[mt][0]), "r"(af[mt][1]), "r"(af[mt][2]), "r"(af[mt][3]),
                          "r"(bf[nt][0]), "r"(bf[nt][1]));
                }
        }
    }

    // Epilogue: write partials (C fragment layout of m16n8)
    float* part = g_part + (size_t)z * (M_TOT * N_TOT);
#pragma unroll
    for (int mt = 0; mt < 4; mt++) {
        const int m = m0 + wm * 64 + mt * 16 + ar;
#pragma unroll
        for (int nt = 0; nt < 4; nt++) {
            const int n = n0 + wn * 32 + nt * 8 + 2 * ac;
            *(float2*)&part[(size_t)m * N_TOT + n]       = make_float2(acc[mt][nt][0], acc[mt][nt][1]);
            *(float2*)&part[(size_t)(m + 8) * N_TOT + n] = make_float2(acc[mt][nt][2], acc[mt][nt][3]);
        }
    }
}

// ---------------------------------------------------------------------------
// Kernel 3: deterministic split-K reduction + bias
// ---------------------------------------------------------------------------
__global__ void reduce_kernel(const float* __restrict__ bias, float* __restrict__ out) {
    const int m = blockIdx.x;
    const int n = threadIdx.x;
    float s = bias[n];
    const float* p = g_part + (size_t)m * N_TOT + n;
#pragma unroll
    for (int zz = 0; zz < SPLITS; zz++)
        s += p[(size_t)zz * (M_TOT * N_TOT)];
    out[(size_t)m * N_TOT + n] = s;
}

// ---------------------------------------------------------------------------
extern "C" void kernel_launch(void* const* d_in, const int* in_sizes, int n_in,
                              void* d_out, int out_size) {
    const float* x        = (const float*)d_in[0];
    const int*   rxd_perm = (const int*)  d_in[1];
    const int*   e_idx    = (const int*)  d_in[2];
    const float* signs    = (const float*)d_in[3];
    const float* W        = (const float*)d_in[4];
    const float* b        = (const float*)d_in[5];
    float* out = (float*)d_out;

    cudaFuncSetAttribute(gemm_kernel, cudaFuncAttributeMaxDynamicSharedMemorySize, GEMM_SMEM);

    prep_kernel<<<dim3(RXD, M_TOT / ROWS_PB), 256>>>(x, rxd_perm, e_idx, signs);
    gemm_kernel<<<dim3(N_TOT / BN, M_TOT / BM, SPLITS), 256, GEMM_SMEM>>>(W);
    reduce_kernel<<<M_TOT, N_TOT>>>(b, out);
}